// round 6
// baseline (speedup 1.0000x reference)
#include <cuda_runtime.h>

#define D         128
#define U         256
#define KC        10
#define GRID_B    148
#define NMAX      131072
#define WB        16             // warps in scatter kernel
#define SPW       4              // spikes per warp per round
#define SROUND    64             // spikes staged per round
#define CAP       16             // max entries per unit per round
#define ROW       132            // stats row stride (floats)
#define XROW      128            // staged x row stride (floats)
#define THREADS_B (WB * 32)

__device__ __align__(16) float g_w[U * D];       // inv_var * mu  (128 KB)
__device__ float g_b[U];
__device__ float g_resp[(size_t)NMAX * KC];
__device__ float g_part[GRID_B * U * (D + 1)];
__device__ int   g_c64;

__device__ __forceinline__ unsigned smem_u32(const void* p) {
    return (unsigned)__cvta_generic_to_shared(p);
}

// ---------------- prep (+ dtype probe in block 0) ---------------------------
__global__ void prep_kernel(const float* __restrict__ means,
                            const float* __restrict__ lnv,
                            const float* __restrict__ lp,
                            const int* __restrict__ candw, int probe_words) {
    int u = blockIdx.x, d = threadIdx.x;
    float iv = expf(-lnv[d]);
    float m  = means[u * D + d];
    float wv = iv * m;
    g_w[u * D + d] = wv;
    float p = wv * m;
    #pragma unroll
    for (int o = 16; o; o >>= 1) p += __shfl_xor_sync(0xffffffffu, p, o);
    __shared__ float red[4];
    __shared__ int any;
    if (threadIdx.x == 0) any = 0;
    if ((threadIdx.x & 31) == 0) red[threadIdx.x >> 5] = p;
    __syncthreads();
    if (threadIdx.x == 0)
        g_b[u] = -0.5f * (red[0] + red[1] + red[2] + red[3]) + lp[u];
    if (blockIdx.x == 0) {
        // int64 little-endian -> all odd 32-bit words are zero
        for (int i = threadIdx.x * 2 + 1; i < probe_words; i += 2 * D)
            if (candw[i] != 0) any = 1;
        __syncthreads();
        if (threadIdx.x == 0) g_c64 = (any == 0) ? 1 : 0;
    }
}

// ---------------- kernel A: logits + softmax -> resp ------------------------
// 8-lane slices (lane = 8*g + i): slice g handles candidate k = 4*p + g,
// lane i covers dims [16i,16i+16). 2 spikes in flight per warp for MLP.
__global__ void __launch_bounds__(512, 1)
resp_kernel(const float* __restrict__ x, const int* __restrict__ candw, int n) {
    const int lane = threadIdx.x & 31;
    const int g    = lane >> 3;
    const int i    = lane & 7;
    const int gw   = (blockIdx.x * blockDim.x + threadIdx.x) >> 5;
    const int nw   = (gridDim.x * blockDim.x) >> 5;
    const int s64  = g_c64;

    for (int s0 = gw * 2; s0 < n; s0 += nw * 2) {
        int  sidx[2] = {s0, s0 + 1};
        bool sv[2]   = {true, s0 + 1 < n};

        float4 xa[2][4];
        int    myu[2] = {0, 0};
        #pragma unroll
        for (int sp = 0; sp < 2; sp++) {
            int s = sv[sp] ? sidx[sp] : s0;
            const float4* xr = (const float4*)x + (size_t)s * 32 + 4 * i;
            xa[sp][0] = __ldcs(xr + 0);
            xa[sp][1] = __ldcs(xr + 1);
            xa[sp][2] = __ldcs(xr + 2);
            xa[sp][3] = __ldcs(xr + 3);
            if (lane < KC)
                myu[sp] = __ldcs(&candw[((size_t)s * KC + lane) << s64]);
        }

        float lg[2][3];
        #pragma unroll
        for (int p = 0; p < 3; p++) {
            int  k  = 4 * p + g;
            bool kv = (k < KC);
            #pragma unroll
            for (int sp = 0; sp < 2; sp++) {
                int u = __shfl_sync(0xffffffffu, myu[sp], kv ? k : 0);
                const float4* wr = (const float4*)g_w + u * 32 + 4 * i;
                float4 w0 = wr[0], w1 = wr[1], w2 = wr[2], w3 = wr[3];
                float dot =
                    fmaf(w0.x, xa[sp][0].x, fmaf(w0.y, xa[sp][0].y,
                    fmaf(w0.z, xa[sp][0].z, fmaf(w0.w, xa[sp][0].w,
                    fmaf(w1.x, xa[sp][1].x, fmaf(w1.y, xa[sp][1].y,
                    fmaf(w1.z, xa[sp][1].z, fmaf(w1.w, xa[sp][1].w,
                    fmaf(w2.x, xa[sp][2].x, fmaf(w2.y, xa[sp][2].y,
                    fmaf(w2.z, xa[sp][2].z, fmaf(w2.w, xa[sp][2].w,
                    fmaf(w3.x, xa[sp][3].x, fmaf(w3.y, xa[sp][3].y,
                    fmaf(w3.z, xa[sp][3].z, w3.w * xa[sp][3].w)))))))))))))));
                dot += __shfl_xor_sync(0xffffffffu, dot, 4);
                dot += __shfl_xor_sync(0xffffffffu, dot, 2);
                dot += __shfl_xor_sync(0xffffffffu, dot, 1);
                lg[sp][p] = kv ? dot + __ldg(&g_b[u]) : -1e30f;
            }
        }

        #pragma unroll
        for (int sp = 0; sp < 2; sp++) {
            if (!sv[sp]) continue;
            float m = fmaxf(fmaxf(lg[sp][0], lg[sp][1]),
                            fmaxf(lg[sp][2], -2.0f));
            m = fmaxf(m, __shfl_xor_sync(0xffffffffu, m, 8));
            m = fmaxf(m, __shfl_xor_sync(0xffffffffu, m, 16));

            float e0 = __expf(lg[sp][0] - m);
            float e1 = __expf(lg[sp][1] - m);
            float e2 = __expf(lg[sp][2] - m);
            float sl = e0 + e1 + e2;     // identical across 8 lanes of group
            sl += __shfl_xor_sync(0xffffffffu, sl, 8);
            sl += __shfl_xor_sync(0xffffffffu, sl, 16);
            float inv = 1.f / (sl + __expf(-2.0f - m));

            if (i < 3) {
                int k = 4 * i + g;
                if (k < KC) {
                    float e = (i == 0) ? e0 : ((i == 1) ? e1 : e2);
                    __stcs(&g_resp[(size_t)sidx[sp] * KC + k], e * inv);
                }
            }
        }
    }
}

// ---------------- kernel B: direct-indexed scatter, 2 barriers/round --------
__global__ void __launch_bounds__(THREADS_B, 1)
scatter_kernel(const float* __restrict__ x, const int* __restrict__ candw,
               int n, int chunk) {
    extern __shared__ float sm[];
    float* stats = sm;                                   // U*ROW      135 KB
    float* xs    = sm + U * ROW;                         // SROUND*XROW 32 KB
    int2*  ent   = (int2*)(xs + SROUND * XROW);          // U*CAP       32 KB
    int*   cnt   = (int*)(ent + U * CAP);                // U            1 KB

    const int tid = threadIdx.x, lane = tid & 31, w = tid >> 5;
    const int s64 = g_c64;

    for (int i = tid; i < (U * ROW) / 4; i += THREADS_B)
        ((float4*)stats)[i] = make_float4(0.f, 0.f, 0.f, 0.f);
    for (int i = tid; i < U; i += THREADS_B) cnt[i] = 0;

    const int base   = blockIdx.x * chunk;
    const int end    = (base + chunk < n) ? (base + chunk) : n;
    const int rounds = (end - base + SROUND - 1) / SROUND;

    // ---- prologue: x copies + cand/resp regs for round 0 ----
    int uu[SPW]; float rr[SPW];
    {
        #pragma unroll
        for (int j = 0; j < SPW; j++) {
            int sl = w * SPW + j;
            int s  = base + sl;
            if (s < end) {
                unsigned dst = smem_u32(xs + sl * XROW + lane * 4);
                asm volatile("cp.async.cg.shared.global [%0], [%1], 16;\n"
                             :: "r"(dst), "l"(x + (size_t)s * D + lane * 4));
            }
            uu[j] = -1;
            if (s < end && lane < KC) {
                int u = __ldcs(&candw[((size_t)s * KC + lane) << s64]);
                if ((unsigned)u < U) {
                    uu[j] = u;
                    rr[j] = __ldcs(&g_resp[(size_t)s * KC + lane]);
                }
            }
        }
        asm volatile("cp.async.commit_group;\n");
    }
    __syncthreads();   // covers stats/cnt zeroing too

    for (int rd = 0; rd < rounds; rd++) {
        const int rb = base + rd * SROUND;

        // ---- 1. histogram + direct entry write (from prefetched regs) ----
        #pragma unroll
        for (int j = 0; j < SPW; j++) {
            if (uu[j] >= 0) {
                int u = uu[j];
                int slot = atomicAdd(&cnt[u], 1);
                if (slot < CAP) {
                    int2 e;
                    e.x = w * SPW + j;
                    e.y = __float_as_int(rr[j]);
                    ent[u * CAP + slot] = e;
                }
            }
        }

        // ---- 2. prefetch cand/resp for round rd+1 (overlaps with drain) ----
        int nuu[SPW]; float nrr[SPW];
        #pragma unroll
        for (int j = 0; j < SPW; j++) {
            nuu[j] = -1;
            int s = rb + SROUND + w * SPW + j;
            if (s < end && lane < KC) {
                int u = __ldcs(&candw[((size_t)s * KC + lane) << s64]);
                if ((unsigned)u < U) {
                    nuu[j] = u;
                    nrr[j] = __ldcs(&g_resp[(size_t)s * KC + lane]);
                }
            }
        }

        asm volatile("cp.async.wait_group 0;\n" ::: "memory");
        __syncthreads();    // ent + cnt + xs(rd) ready

        // ---- 3. warp w drains its 16 units; resets its own counters ----
        #pragma unroll 2
        for (int u = w * 16; u < w * 16 + 16; u++) {
            int c = cnt[u];
            if (c == 0) continue;
            cnt[u] = 0;                         // owner-exclusive reset
            c = (c < CAP) ? c : CAP;
            float4* rowp = (float4*)(stats + u * ROW);
            float4 f = rowp[lane];
            float csum = 0.f;
            const int2* eb = ent + u * CAP;
            for (int i = 0; i < c; i++) {
                int2 e = eb[i];
                float r = __int_as_float(e.y);
                float4 xv = ((const float4*)(xs + e.x * XROW))[lane];
                f.x = fmaf(r, xv.x, f.x);
                f.y = fmaf(r, xv.y, f.y);
                f.z = fmaf(r, xv.z, f.z);
                f.w = fmaf(r, xv.w, f.w);
                csum += r;
            }
            rowp[lane] = f;
            if (lane == 0) stats[u * ROW + 128] += csum;
        }
        __syncthreads();    // xs/ent free, cnt resets visible

        // ---- 4. issue x copies for round rd+1 ----
        if (rd + 1 < rounds) {
            #pragma unroll
            for (int j = 0; j < SPW; j++) {
                int sl = w * SPW + j;
                int s  = rb + SROUND + sl;
                if (s < end) {
                    unsigned dst = smem_u32(xs + sl * XROW + lane * 4);
                    asm volatile("cp.async.cg.shared.global [%0], [%1], 16;\n"
                                 :: "r"(dst), "l"(x + (size_t)s * D + lane * 4));
                }
            }
            asm volatile("cp.async.commit_group;\n");
        }
        #pragma unroll
        for (int j = 0; j < SPW; j++) { uu[j] = nuu[j]; rr[j] = nrr[j]; }
    }

    for (int i = tid; i < U * (D + 1); i += THREADS_B) {
        int u = i / (D + 1);
        int d = i - u * (D + 1);
        g_part[blockIdx.x * (U * (D + 1)) + i] = stats[u * ROW + d];
    }
}

// ---------------- final reduction: 64 outputs x 4 slices per block ----------
__global__ void reduce_kernel(float* __restrict__ out) {
    __shared__ float red[4][64];
    const int ol    = threadIdx.x & 63;
    const int slice = threadIdx.x >> 6;
    const int o     = blockIdx.x * 64 + ol;
    const int pb    = slice * 37;
    const int pe    = (pb + 37 < GRID_B) ? pb + 37 : GRID_B;
    float s0 = 0.f, s1 = 0.f, s2 = 0.f, s3 = 0.f;
    int p = pb;
    for (; p + 4 <= pe; p += 4) {
        s0 += g_part[(p + 0) * (U * (D + 1)) + o];
        s1 += g_part[(p + 1) * (U * (D + 1)) + o];
        s2 += g_part[(p + 2) * (U * (D + 1)) + o];
        s3 += g_part[(p + 3) * (U * (D + 1)) + o];
    }
    for (; p < pe; p++) s0 += g_part[p * (U * (D + 1)) + o];
    red[slice][ol] = (s0 + s1) + (s2 + s3);
    __syncthreads();
    if (slice == 0)
        out[o] = (red[0][ol] + red[1][ol]) + (red[2][ol] + red[3][ol]);
}

extern "C" void kernel_launch(void* const* d_in, const int* in_sizes, int n_in,
                              void* d_out, int out_size) {
    const float* feats = (const float*)d_in[0];
    const float* means = (const float*)d_in[1];
    const float* lnv   = (const float*)d_in[2];
    const float* lp    = (const float*)d_in[3];
    const int*   candw = (const int*)d_in[4];

    int n  = in_sizes[0] / D;
    int nK = in_sizes[4];
    int probe_words = nK < 4096 ? nK : 4096;

    prep_kernel<<<U, D>>>(means, lnv, lp, candw, probe_words);
    resp_kernel<<<GRID_B, 512>>>(feats, candw, n);

    int chunk = (n + GRID_B - 1) / GRID_B;
    size_t smem = (size_t)U * ROW * sizeof(float)
                + (size_t)SROUND * XROW * sizeof(float)
                + (size_t)U * CAP * sizeof(int2)
                + (size_t)U * sizeof(int);
    cudaFuncSetAttribute(scatter_kernel,
                         cudaFuncAttributeMaxDynamicSharedMemorySize, (int)smem);
    scatter_kernel<<<GRID_B, THREADS_B, smem>>>(feats, candw, n, chunk);

    reduce_kernel<<<(U * (D + 1)) / 64, 256>>>((float*)d_out);
}

// round 7
// speedup vs baseline: 1.0314x; 1.0314x over previous
#include <cuda_runtime.h>

#define D         128
#define U         256
#define KC        10
#define GRID_B    148
#define NMAX      131072
#define WB        16             // warps in scatter kernel
#define SPW       4              // spikes per warp per round
#define SROUND    64             // spikes staged per round
#define CAP       16             // max entries per unit per round
#define XROW      128            // staged x row stride (floats)
#define PROW      132            // g_part row stride (floats, 16B aligned)
#define THREADS_B (WB * 32)

__device__ __align__(16) float g_w[U * D];       // inv_var * mu  (128 KB)
__device__ float g_b[U];
__device__ float g_resp[(size_t)NMAX * KC];
__device__ __align__(16) float g_part[GRID_B * U * PROW];
__device__ int   g_c64;

__device__ __forceinline__ unsigned smem_u32(const void* p) {
    return (unsigned)__cvta_generic_to_shared(p);
}

// ---------------- prep (+ dtype probe in block 0) ---------------------------
__global__ void prep_kernel(const float* __restrict__ means,
                            const float* __restrict__ lnv,
                            const float* __restrict__ lp,
                            const int* __restrict__ candw, int probe_words) {
    int u = blockIdx.x, d = threadIdx.x;
    float iv = expf(-lnv[d]);
    float m  = means[u * D + d];
    float wv = iv * m;
    g_w[u * D + d] = wv;
    float p = wv * m;
    #pragma unroll
    for (int o = 16; o; o >>= 1) p += __shfl_xor_sync(0xffffffffu, p, o);
    __shared__ float red[4];
    __shared__ int any;
    if (threadIdx.x == 0) any = 0;
    if ((threadIdx.x & 31) == 0) red[threadIdx.x >> 5] = p;
    __syncthreads();
    if (threadIdx.x == 0)
        g_b[u] = -0.5f * (red[0] + red[1] + red[2] + red[3]) + lp[u];
    if (blockIdx.x == 0) {
        // int64 little-endian -> all odd 32-bit words are zero
        for (int i = threadIdx.x * 2 + 1; i < probe_words; i += 2 * D)
            if (candw[i] != 0) any = 1;
        __syncthreads();
        if (threadIdx.x == 0) g_c64 = (any == 0) ? 1 : 0;
    }
}

// ---------------- kernel A: logits + softmax -> resp ------------------------
// 8-lane slices (lane = 8*g + i): slice g handles candidate k = 4*p + g,
// lane i covers dims [16i,16i+16). 2 spikes in flight per warp.
__global__ void __launch_bounds__(256)
resp_kernel(const float* __restrict__ x, const int* __restrict__ candw, int n) {
    const int lane = threadIdx.x & 31;
    const int g    = lane >> 3;
    const int i    = lane & 7;
    const int gw   = (blockIdx.x * blockDim.x + threadIdx.x) >> 5;
    const int nw   = (gridDim.x * blockDim.x) >> 5;
    const int s64  = g_c64;

    for (int s0 = gw * 2; s0 < n; s0 += nw * 2) {
        int  sidx[2] = {s0, s0 + 1};
        bool sv[2]   = {true, s0 + 1 < n};

        float4 xa[2][4];
        int    myu[2] = {0, 0};
        #pragma unroll
        for (int sp = 0; sp < 2; sp++) {
            int s = sv[sp] ? sidx[sp] : s0;
            const float4* xr = (const float4*)x + (size_t)s * 32 + 4 * i;
            xa[sp][0] = __ldcs(xr + 0);
            xa[sp][1] = __ldcs(xr + 1);
            xa[sp][2] = __ldcs(xr + 2);
            xa[sp][3] = __ldcs(xr + 3);
            if (lane < KC)
                myu[sp] = __ldcs(&candw[((size_t)s * KC + lane) << s64]);
        }

        float lg[2][3];
        #pragma unroll
        for (int p = 0; p < 3; p++) {
            int  k  = 4 * p + g;
            bool kv = (k < KC);
            #pragma unroll
            for (int sp = 0; sp < 2; sp++) {
                int u = __shfl_sync(0xffffffffu, myu[sp], kv ? k : 0);
                const float4* wr = (const float4*)g_w + u * 32 + 4 * i;
                float4 w0 = wr[0], w1 = wr[1], w2 = wr[2], w3 = wr[3];
                float dot =
                    fmaf(w0.x, xa[sp][0].x, fmaf(w0.y, xa[sp][0].y,
                    fmaf(w0.z, xa[sp][0].z, fmaf(w0.w, xa[sp][0].w,
                    fmaf(w1.x, xa[sp][1].x, fmaf(w1.y, xa[sp][1].y,
                    fmaf(w1.z, xa[sp][1].z, fmaf(w1.w, xa[sp][1].w,
                    fmaf(w2.x, xa[sp][2].x, fmaf(w2.y, xa[sp][2].y,
                    fmaf(w2.z, xa[sp][2].z, fmaf(w2.w, xa[sp][2].w,
                    fmaf(w3.x, xa[sp][3].x, fmaf(w3.y, xa[sp][3].y,
                    fmaf(w3.z, xa[sp][3].z, w3.w * xa[sp][3].w)))))))))))))));
                dot += __shfl_xor_sync(0xffffffffu, dot, 4);
                dot += __shfl_xor_sync(0xffffffffu, dot, 2);
                dot += __shfl_xor_sync(0xffffffffu, dot, 1);
                lg[sp][p] = kv ? dot + __ldg(&g_b[u]) : -1e30f;
            }
        }

        #pragma unroll
        for (int sp = 0; sp < 2; sp++) {
            if (!sv[sp]) continue;
            float m = fmaxf(fmaxf(lg[sp][0], lg[sp][1]),
                            fmaxf(lg[sp][2], -2.0f));
            m = fmaxf(m, __shfl_xor_sync(0xffffffffu, m, 8));
            m = fmaxf(m, __shfl_xor_sync(0xffffffffu, m, 16));

            float e0 = __expf(lg[sp][0] - m);
            float e1 = __expf(lg[sp][1] - m);
            float e2 = __expf(lg[sp][2] - m);
            float sl = e0 + e1 + e2;     // identical across 8 lanes of group
            sl += __shfl_xor_sync(0xffffffffu, sl, 8);
            sl += __shfl_xor_sync(0xffffffffu, sl, 16);
            float inv = 1.f / (sl + __expf(-2.0f - m));

            if (i < 3) {
                int k = 4 * i + g;
                if (k < KC) {
                    float e = (i == 0) ? e0 : ((i == 1) ? e1 : e2);
                    __stcs(&g_resp[(size_t)sidx[sp] * KC + k], e * inv);
                }
            }
        }
    }
}

// ---------------- kernel B: scatter with REGISTER-resident stats ------------
// Warp w owns units [16w,16w+16); lane holds dims [4*lane,4*lane+4) of each.
__global__ void __launch_bounds__(THREADS_B, 1)
scatter_kernel(const float* __restrict__ x, const int* __restrict__ candw,
               int n, int chunk) {
    extern __shared__ float sm[];
    float* xs   = sm;                                // 2 * SROUND*XROW (64 KB)
    int2*  ent  = (int2*)(xs + 2 * SROUND * XROW);   // U*CAP           (32 KB)
    int*   cnt  = (int*)(ent + U * CAP);             // U
    float* cntF = (float*)(cnt + U);                 // U (soft counts)

    const int tid = threadIdx.x, lane = tid & 31, w = tid >> 5;
    const int s64 = g_c64;

    float4 acc[16];
    #pragma unroll
    for (int j = 0; j < 16; j++) acc[j] = make_float4(0.f, 0.f, 0.f, 0.f);

    for (int i = tid; i < U; i += THREADS_B) { cnt[i] = 0; cntF[i] = 0.f; }

    const int base   = blockIdx.x * chunk;
    const int end    = (base + chunk < n) ? (base + chunk) : n;
    const int rounds = (end - base + SROUND - 1) / SROUND;

    // ---- prologue: x copies (buf 0) + cand/resp regs for round 0 ----
    int uu[SPW]; float rr[SPW];
    #pragma unroll
    for (int j = 0; j < SPW; j++) {
        int sl = w * SPW + j;
        int s  = base + sl;
        if (s < end) {
            unsigned dst = smem_u32(xs + sl * XROW + lane * 4);
            asm volatile("cp.async.cg.shared.global [%0], [%1], 16;\n"
                         :: "r"(dst), "l"(x + (size_t)s * D + lane * 4));
        }
        uu[j] = -1;
        if (s < end && lane < KC) {
            int u = __ldcs(&candw[((size_t)s * KC + lane) << s64]);
            if ((unsigned)u < U) {
                uu[j] = u;
                rr[j] = __ldcs(&g_resp[(size_t)s * KC + lane]);
            }
        }
    }
    asm volatile("cp.async.commit_group;\n");
    __syncthreads();                 // cnt zeroing + prologue ordering

    for (int rd = 0; rd < rounds; rd++) {
        const int   rb  = base + rd * SROUND;
        const float* xsb = xs + (rd & 1) * SROUND * XROW;

        // ---- 1. histogram + direct entry write (prefetched regs) ----
        #pragma unroll
        for (int j = 0; j < SPW; j++) {
            if (uu[j] >= 0) {
                int u = uu[j];
                int slot = atomicAdd(&cnt[u], 1);
                if (slot < CAP) {
                    int2 e;
                    e.x = w * SPW + j;
                    e.y = __float_as_int(rr[j]);
                    ent[u * CAP + slot] = e;
                }
            }
        }

        // ---- 2. prefetch cand/resp for rd+1; issue xs copies for rd+1 ----
        #pragma unroll
        for (int j = 0; j < SPW; j++) {
            int s = rb + SROUND + w * SPW + j;
            int nu = -1; float nr = 0.f;
            if (s < end && lane < KC) {
                int u = __ldcs(&candw[((size_t)s * KC + lane) << s64]);
                if ((unsigned)u < U) {
                    nu = u;
                    nr = __ldcs(&g_resp[(size_t)s * KC + lane]);
                }
            }
            uu[j] = nu; rr[j] = nr;
        }
        if (rd + 1 < rounds) {
            float* xsn = xs + ((rd + 1) & 1) * SROUND * XROW;
            #pragma unroll
            for (int j = 0; j < SPW; j++) {
                int sl = w * SPW + j;
                int s  = rb + SROUND + sl;
                if (s < end) {
                    unsigned dst = smem_u32(xsn + sl * XROW + lane * 4);
                    asm volatile("cp.async.cg.shared.global [%0], [%1], 16;\n"
                                 :: "r"(dst), "l"(x + (size_t)s * D + lane * 4));
                }
            }
        }
        asm volatile("cp.async.commit_group;\n");
        asm volatile("cp.async.wait_group 1;\n" ::: "memory"); // xs(rd) ready
        __syncthreads();                       // ent/cnt complete

        // ---- 3. warp w drains its 16 units into register accumulators ----
        #pragma unroll
        for (int j = 0; j < 16; j++) {
            int u = w * 16 + j;
            int c = cnt[u];
            if (c == 0) continue;
            if (lane == 0) cnt[u] = 0;
            c = (c < CAP) ? c : CAP;
            float csum = 0.f;
            const int2* eb = ent + u * CAP;
            for (int i2 = 0; i2 < c; i2++) {
                int2 e = eb[i2];
                float r = __int_as_float(e.y);
                float4 xv = ((const float4*)(xsb + e.x * XROW))[lane];
                acc[j].x = fmaf(r, xv.x, acc[j].x);
                acc[j].y = fmaf(r, xv.y, acc[j].y);
                acc[j].z = fmaf(r, xv.z, acc[j].z);
                acc[j].w = fmaf(r, xv.w, acc[j].w);
                csum += r;
            }
            if (lane == 0) cntF[u] += csum;
        }
        __syncthreads();   // cnt resets visible; ent reusable next round
    }

    // ---- flush register stats ----
    float* pb = g_part + (size_t)blockIdx.x * (U * PROW);
    #pragma unroll
    for (int j = 0; j < 16; j++) {
        int u = w * 16 + j;
        ((float4*)(pb + u * PROW))[lane] = acc[j];
        if (lane == 0) pb[u * PROW + 128] = cntF[u];
    }
}

// ---------------- final reduction: 64 outputs x 4 slices per block ----------
__global__ void reduce_kernel(float* __restrict__ out) {
    __shared__ float red[4][64];
    const int ol    = threadIdx.x & 63;
    const int slice = threadIdx.x >> 6;
    const int o     = blockIdx.x * 64 + ol;
    if (o >= U * (D + 1)) return;
    const int u = o / (D + 1);
    const int d = o - u * (D + 1);
    const int idx = u * PROW + d;
    const int pb = slice * 37;
    const int pe = (pb + 37 < GRID_B) ? pb + 37 : GRID_B;
    float s0 = 0.f, s1 = 0.f, s2 = 0.f, s3 = 0.f;
    int p = pb;
    for (; p + 4 <= pe; p += 4) {
        s0 += g_part[(size_t)(p + 0) * (U * PROW) + idx];
        s1 += g_part[(size_t)(p + 1) * (U * PROW) + idx];
        s2 += g_part[(size_t)(p + 2) * (U * PROW) + idx];
        s3 += g_part[(size_t)(p + 3) * (U * PROW) + idx];
    }
    for (; p < pe; p++) s0 += g_part[(size_t)p * (U * PROW) + idx];
    red[slice][ol] = (s0 + s1) + (s2 + s3);
    __syncthreads();
    if (slice == 0)
        out[o] = (red[0][ol] + red[1][ol]) + (red[2][ol] + red[3][ol]);
}

extern "C" void kernel_launch(void* const* d_in, const int* in_sizes, int n_in,
                              void* d_out, int out_size) {
    const float* feats = (const float*)d_in[0];
    const float* means = (const float*)d_in[1];
    const float* lnv   = (const float*)d_in[2];
    const float* lp    = (const float*)d_in[3];
    const int*   candw = (const int*)d_in[4];

    int n  = in_sizes[0] / D;
    int nK = in_sizes[4];
    int probe_words = nK < 4096 ? nK : 4096;

    prep_kernel<<<U, D>>>(means, lnv, lp, candw, probe_words);
    resp_kernel<<<GRID_B * 4, 256>>>(feats, candw, n);

    int chunk = (n + GRID_B - 1) / GRID_B;
    size_t smem = (size_t)2 * SROUND * XROW * sizeof(float)
                + (size_t)U * CAP * sizeof(int2)
                + (size_t)U * (sizeof(int) + sizeof(float));
    cudaFuncSetAttribute(scatter_kernel,
                         cudaFuncAttributeMaxDynamicSharedMemorySize, (int)smem);
    scatter_kernel<<<GRID_B, THREADS_B, smem>>>(feats, candw, n, chunk);

    int total = U * (D + 1);
    reduce_kernel<<<(total + 63) / 64, 256>>>((float*)d_out);
}